// round 11
// baseline (speedup 1.0000x reference)
#include <cuda_runtime.h>
#include <cuda_bf16.h>
#include <cstdint>
#include <cstddef>

#define BB 128
#define TT 64
#define HH 256
#define VV 128
#define G3H 768

// ---------------- persistent scratch ----------------
__device__ float g_xp [BB*TT*G3H];     // input projections (both layers, reused)
__device__ float g_seq[BB*TT*HH];      // layer-0 output
__device__ float g_enc[BB*TT*HH];      // layer-1 output (encoder)
__device__ float g_Wa [BB*TT*HH];
__device__ float g_Ua [BB*TT*HH];
__device__ float g_ctx[BB*TT*HH];

// ---------------- helpers ----------------
union F2U { float2 f; unsigned long long u; };

__device__ __forceinline__ float2 ffma2(float2 a, float2 b, float2 c) {
    F2U A, B, C, D; A.f = a; B.f = b; C.f = c;
    asm("fma.rn.f32x2 %0, %1, %2, %3;" : "=l"(D.u) : "l"(A.u), "l"(B.u), "l"(C.u));
    return D.f;
}

__device__ __forceinline__ float4 ffma4(float a, float4 b, float4 c) {
    float2 p = ffma2(make_float2(a, a), make_float2(b.x, b.y), make_float2(c.x, c.y));
    float2 q = ffma2(make_float2(a, a), make_float2(b.z, b.w), make_float2(c.z, c.w));
    return make_float4(p.x, p.y, q.x, q.y);
}

__device__ __forceinline__ float tanha(float x) {
    float y; asm("tanh.approx.f32 %0, %1;" : "=f"(y) : "f"(x)); return y;
}

__device__ __forceinline__ float sigm(float x) {
    return 1.f / (1.f + __expf(-x));
}

__device__ __forceinline__ uint32_t smem_u32(const void* p) {
    uint32_t a;
    asm("{ .reg .u64 t; cvta.to.shared.u64 t, %1; cvt.u32.u64 %0, t; }" : "=r"(a) : "l"(p));
    return a;
}

#define MBARRIER_INIT(addr, cnt) \
    asm volatile("mbarrier.init.shared.b64 [%0], %1;" :: "r"(addr), "r"(cnt) : "memory")

#define MBARRIER_EXPECT_TX(addr, tx) \
    asm volatile("mbarrier.arrive.expect_tx.shared.b64 _, [%0], %1;" :: "r"(addr), "r"(tx) : "memory")

#define MBARRIER_WAIT_PARITY(addr, par) do {                                        \
    uint32_t _m = (addr); uint32_t _p = (par); uint32_t _done;                      \
    asm volatile("{\n\t.reg .pred p;\n\t"                                           \
        "mbarrier.try_wait.parity.acquire.cta.shared::cta.b64 p, [%1], %2;\n\t"     \
        "selp.b32 %0, 1, 0, p;\n\t}"                                                \
        : "=r"(_done) : "r"(_m), "r"(_p) : "memory");                               \
    if (!_done) {                                                                   \
        asm volatile("{\n\t.reg .pred P1;\n\t"                                      \
            "WL_%=:\n\t"                                                            \
            "mbarrier.try_wait.parity.acquire.cta.shared::cta.b64 P1, [%0], %1, 0x989680;\n\t" \
            "@P1 bra.uni WD_%=;\n\t"                                                \
            "bra.uni WL_%=;\n\t"                                                    \
            "WD_%=:\n\t}" :: "r"(_m), "r"(_p) : "memory");                          \
    }                                                                               \
} while (0)

#define ST_ASYNC_B32(raddr, uval, rmbar) \
    asm volatile("st.async.shared::cluster.mbarrier::complete_tx::bytes.b32 [%0], %1, [%2];" \
        :: "r"(raddr), "r"(uval), "r"(rmbar) : "memory")

#define MAPA_U32(dst, laddr, rank) \
    asm("mapa.shared::cluster.u32 %0, %1, %2;" : "=r"(dst) : "r"(laddr), "r"(rank))

#define CLUSTER_SYNC() do {                                              \
    asm volatile("barrier.cluster.arrive.aligned;" ::: "memory");        \
    asm volatile("barrier.cluster.wait.aligned;" ::: "memory");          \
} while (0)

// ---------------- GEMM: C[m,n] = sum_k A[m,k]*W[n,k] (+bias | +=C) ----------------
// BM=128 BN=64 BK=16, 256 threads, 8x4 per thread, f32x2 FMA, register-staged
// k-tile pipelining. gather != null: A row m is A + gather[m]*lda.
__global__ void __launch_bounds__(256)
gemm_k(const float* __restrict__ A, int lda, const int* __restrict__ gather,
       const float* __restrict__ W, int ldw,
       const float* __restrict__ bias,
       float* __restrict__ C, int ldc, int K, int accumulate)
{
    __shared__ float As[16 * 132];
    __shared__ float Bs[16 * 68];

    const int tid = threadIdx.x;
    const int tx = tid & 15;           // n
    const int ty = tid >> 4;           // m
    const int mbase = blockIdx.x * 128;
    const int nbase = blockIdx.y * 64;

    // hoisted load pointers
    const int ra = tid >> 2;           // A rows: ra and ra+64
    const int c4 = tid & 3;            // float4 column within 16-wide k-tile
    const int m0 = mbase + ra;
    const int m1 = mbase + ra + 64;
    const float* arow0 = A + (size_t)(gather ? gather[m0] : m0) * lda;
    const float* arow1 = A + (size_t)(gather ? gather[m1] : m1) * lda;
    const float* wrow  = W + (size_t)(nbase + ra) * ldw;

    float4 acc[8];
#pragma unroll
    for (int i = 0; i < 8; ++i) acc[i] = make_float4(0.f, 0.f, 0.f, 0.f);

    const int ktiles = K >> 4;
    float4 Av0 = __ldg((const float4*)(arow0 + c4 * 4));
    float4 Av1 = __ldg((const float4*)(arow1 + c4 * 4));
    float4 Bv  = __ldg((const float4*)(wrow  + c4 * 4));

    for (int kt = 0; kt < ktiles; ++kt) {
        // regs -> smem (transposed)
        As[(c4 * 4 + 0) * 132 + ra]      = Av0.x;
        As[(c4 * 4 + 1) * 132 + ra]      = Av0.y;
        As[(c4 * 4 + 2) * 132 + ra]      = Av0.z;
        As[(c4 * 4 + 3) * 132 + ra]      = Av0.w;
        As[(c4 * 4 + 0) * 132 + ra + 64] = Av1.x;
        As[(c4 * 4 + 1) * 132 + ra + 64] = Av1.y;
        As[(c4 * 4 + 2) * 132 + ra + 64] = Av1.z;
        As[(c4 * 4 + 3) * 132 + ra + 64] = Av1.w;
        Bs[(c4 * 4 + 0) * 68 + ra] = Bv.x;
        Bs[(c4 * 4 + 1) * 68 + ra] = Bv.y;
        Bs[(c4 * 4 + 2) * 68 + ra] = Bv.z;
        Bs[(c4 * 4 + 3) * 68 + ra] = Bv.w;
        __syncthreads();

        if (kt + 1 < ktiles) {            // prefetch next tile while computing
            Av0 = __ldg((const float4*)(arow0 + (kt + 1) * 16 + c4 * 4));
            Av1 = __ldg((const float4*)(arow1 + (kt + 1) * 16 + c4 * 4));
            Bv  = __ldg((const float4*)(wrow  + (kt + 1) * 16 + c4 * 4));
        }

#pragma unroll
        for (int k = 0; k < 16; ++k) {
            float4 a0 = *(const float4*)&As[k * 132 + ty * 8];
            float4 a1 = *(const float4*)&As[k * 132 + ty * 8 + 4];
            float4 b4 = *(const float4*)&Bs[k * 68 + tx * 4];
            acc[0] = ffma4(a0.x, b4, acc[0]);
            acc[1] = ffma4(a0.y, b4, acc[1]);
            acc[2] = ffma4(a0.z, b4, acc[2]);
            acc[3] = ffma4(a0.w, b4, acc[3]);
            acc[4] = ffma4(a1.x, b4, acc[4]);
            acc[5] = ffma4(a1.y, b4, acc[5]);
            acc[6] = ffma4(a1.z, b4, acc[6]);
            acc[7] = ffma4(a1.w, b4, acc[7]);
        }
        __syncthreads();
    }

    const int n0 = nbase + tx * 4;
    float4 bv = make_float4(0.f, 0.f, 0.f, 0.f);
    if (bias) bv = *(const float4*)&bias[n0];
#pragma unroll
    for (int mi = 0; mi < 8; ++mi) {
        int m = mbase + ty * 8 + mi;
        float4* cp = (float4*)&C[(size_t)m * ldc + n0];
        float4 o = acc[mi];
        if (accumulate) {
            float4 old = *cp;
            o.x += old.x; o.y += old.y; o.z += old.z; o.w += old.w;
        } else {
            o.x += bv.x; o.y += bv.y; o.z += bv.z; o.w += bv.w;
        }
        *cp = o;
    }
}

// ---------------- GRU scan: 32 clusters x 4 CTAs, DSMEM h exchange ----------------
// CTA (cluster rank c) owns j-slice [64c, 64c+64) for 4 batches; its 192x256
// w_hh slice (196KB) stays L1-resident — NO gpu-scope fences anywhere in the loop.
// h exchange: every thread st.async's its h value into all 4 CTAs' smem buffer
// (double-buffered by step parity) with mbarrier complete_tx accounting.
__global__ void __launch_bounds__(256, 1) __cluster_dims__(4, 1, 1)
scan_k(const float* __restrict__ xp, const float* __restrict__ w_hh,
       const float* __restrict__ b_hh, float* __restrict__ seq,
       float* __restrict__ hlast)
{
    __shared__ __align__(16) float hbuf[2][4][256];       // 8KB, [parity][b][j]
    __shared__ __align__(8) unsigned long long mbar[2];

    const int g   = blockIdx.x >> 2;
    const int tid = threadIdx.x;
    const int j   = tid >> 2;                 // 0..63
    const int kq  = tid & 3;                  // k-quarter == local batch lane
    uint32_t rank;
    asm("mov.u32 %0, %%cluster_ctarank;" : "=r"(rank));
    const int jg = (int)rank * 64 + j;
    const int b0 = g * 4;

    const float4* w0 = (const float4*)(w_hh + (size_t)(0 * 256 + jg) * 256);
    const float4* w1 = (const float4*)(w_hh + (size_t)(1 * 256 + jg) * 256);
    const float4* w2 = (const float4*)(w_hh + (size_t)(2 * 256 + jg) * 256);
    const float bh0 = b_hh[jg], bh1 = b_hh[256 + jg], bh2 = b_hh[512 + jg];

    const uint32_t mb0  = smem_u32(&mbar[0]);
    const uint32_t myh  = smem_u32(&hbuf[0][kq][jg]);   // where MY value lives
    uint32_t rh[4], rm[4];
#pragma unroll
    for (int r = 0; r < 4; ++r) { MAPA_U32(rh[r], myh, r); MAPA_U32(rm[r], mb0, r); }

    if (tid == 0) { MBARRIER_INIT(mb0, 1); MBARRIER_INIT(mb0 + 8, 1); }
    __syncthreads();
    CLUSTER_SYNC();                       // all mbars live before any st.async
    if (tid == 0) {                       // open phase 0 of both barriers
        MBARRIER_EXPECT_TX(mb0, 4096);
        MBARRIER_EXPECT_TX(mb0 + 8, 4096);
    }

    const float* xpb = xp + (size_t)(b0 + kq) * TT * G3H;
    float hprev = 0.f;
    int ph0 = 0, ph1 = 0;

    for (int t = 0; t < TT; ++t) {
        // prefetch xp for this (b, t) — latency hidden under wait+compute
        const float* xr_p = xpb + (size_t)t * G3H;
        const float xr = __ldcg(xr_p + jg);
        const float xz = __ldcg(xr_p + 256 + jg);
        const float xn = __ldcg(xr_p + 512 + jg);

        float hr, hz, hn;
        if (t == 0) {
            hr = bh0; hz = bh1; hn = bh2;   // h == 0 -> matvec is zero
        } else {
            const int ip = (t - 1) & 1;
            if (ip == 0) { MBARRIER_WAIT_PARITY(mb0, ph0);     ph0 ^= 1; }
            else         { MBARRIER_WAIT_PARITY(mb0 + 8, ph1); ph1 ^= 1; }
            if (tid == 0) MBARRIER_EXPECT_TX(mb0 + 8 * ip, 4096);  // re-arm next use

            float2 s0[4], s1[4], s2[4];
#pragma unroll
            for (int b = 0; b < 4; ++b) {
                s0[b] = make_float2(0.f, 0.f);
                s1[b] = make_float2(0.f, 0.f);
                s2[b] = make_float2(0.f, 0.f);
            }
#pragma unroll 4
            for (int i = 0; i < 16; ++i) {
                const int f4 = i * 4 + kq;
                float4 wv0 = __ldg(w0 + f4);       // L1-resident across steps
                float4 wv1 = __ldg(w1 + f4);
                float4 wv2 = __ldg(w2 + f4);
#pragma unroll
                for (int b = 0; b < 4; ++b) {
                    float4 hv = *(const float4*)&hbuf[ip][b][f4 << 2];
                    s0[b] = ffma2(make_float2(wv0.x, wv0.y), make_float2(hv.x, hv.y), s0[b]);
                    s0[b] = ffma2(make_float2(wv0.z, wv0.w), make_float2(hv.z, hv.w), s0[b]);
                    s1[b] = ffma2(make_float2(wv1.x, wv1.y), make_float2(hv.x, hv.y), s1[b]);
                    s1[b] = ffma2(make_float2(wv1.z, wv1.w), make_float2(hv.z, hv.w), s1[b]);
                    s2[b] = ffma2(make_float2(wv2.x, wv2.y), make_float2(hv.x, hv.y), s2[b]);
                    s2[b] = ffma2(make_float2(wv2.z, wv2.w), make_float2(hv.z, hv.w), s2[b]);
                }
            }
            // reduce the 4 k-quarters across the quad; every lane ends with full sums
#pragma unroll
            for (int b = 0; b < 4; ++b) {
#pragma unroll
                for (int m = 1; m <= 2; m <<= 1) {
                    s0[b].x += __shfl_xor_sync(0xffffffffu, s0[b].x, m);
                    s0[b].y += __shfl_xor_sync(0xffffffffu, s0[b].y, m);
                    s1[b].x += __shfl_xor_sync(0xffffffffu, s1[b].x, m);
                    s1[b].y += __shfl_xor_sync(0xffffffffu, s1[b].y, m);
                    s2[b].x += __shfl_xor_sync(0xffffffffu, s2[b].x, m);
                    s2[b].y += __shfl_xor_sync(0xffffffffu, s2[b].y, m);
                }
            }
            float2 t0 = s0[0], t1 = s1[0], t2 = s2[0];
            if (kq == 1) { t0 = s0[1]; t1 = s1[1]; t2 = s2[1]; }
            else if (kq == 2) { t0 = s0[2]; t1 = s1[2]; t2 = s2[2]; }
            else if (kq == 3) { t0 = s0[3]; t1 = s1[3]; t2 = s2[3]; }
            hr = t0.x + t0.y + bh0;
            hz = t1.x + t1.y + bh1;
            hn = t2.x + t2.y + bh2;
        }

        const float r = sigm(xr + hr);
        const float z = sigm(xz + hz);
        const float n = tanhf(xn + r * hn);
        const float hnew = (1.f - z) * n + z * hprev;
        hprev = hnew;

        __stcg(&seq[((size_t)(b0 + kq) * TT + t) * HH + jg], hnew);
        if (hlast != nullptr && t == TT - 1)
            __stcg(&hlast[(size_t)(b0 + kq) * HH + jg], hnew);

        // broadcast my h value to all 4 CTAs' buffer[t&1]
        const uint32_t po = (uint32_t)(t & 1);
        const uint32_t uval = __float_as_uint(hnew);
#pragma unroll
        for (int r2 = 0; r2 < 4; ++r2)
            ST_ASYNC_B32(rh[r2] + po * 4096u, uval, rm[r2] + po * 8u);
    }

    // drain: h(63) landed in mbar[1]'s final phase; consume it so no st.async
    // targets our smem after exit, then cluster-sync out.
    MBARRIER_WAIT_PARITY(mb0 + 8, ph1);
    CLUSTER_SYNC();
}

// ---------------- attention (CTA per batch) ----------------
#define AT_SMEM_FLOATS (2 * 64 * 260 + 64 * 68 + 256)
#define AT_SMEM_BYTES  (AT_SMEM_FLOATS * 4)

__global__ void __launch_bounds__(256, 1)
attn_k(const float* __restrict__ Wa, const float* __restrict__ Ua,
       const float* __restrict__ enc, const float* __restrict__ va,
       float* __restrict__ ctx)
{
    extern __shared__ float sm[];
    float* WA = sm;
    float* UA = sm + 64 * 260;
    float* ES = sm + 2 * 64 * 260;
    float* VS = ES + 64 * 68;

    const int b = blockIdx.x;
    const int tid = threadIdx.x;
    const float* waB = Wa + (size_t)b * 64 * 256;
    const float* uaB = Ua + (size_t)b * 64 * 256;

    for (int idx = tid; idx < 4096; idx += 256) {
        int k = idx >> 6, h4 = idx & 63;
        float4 w4 = __ldg((const float4*)waB + idx);
        *(float4*)&WA[k * 260 + ((h4 ^ (k & 7)) << 2)] = w4;   // xor swizzle
        float4 u4 = __ldg((const float4*)uaB + idx);
        *(float4*)&UA[k * 260 + (h4 << 2)] = u4;
    }
    if (tid < 64) *(float4*)&VS[tid * 4] = __ldg((const float4*)va + tid);
    __syncthreads();

    const int tq = tid >> 3, kq = tid & 7;
    const int t0 = tq * 2;
    float e0[8], e1[8];
#pragma unroll
    for (int i = 0; i < 8; ++i) { e0[i] = 0.f; e1[i] = 0.f; }

    for (int h4 = 0; h4 < 64; ++h4) {
        float4 v4 = *(const float4*)&VS[h4 * 4];
        float4 uA = *(const float4*)&UA[t0 * 260 + h4 * 4];
        float4 uB = *(const float4*)&UA[(t0 + 1) * 260 + h4 * 4];
#pragma unroll
        for (int i = 0; i < 8; ++i) {
            int k = i * 8 + kq;
            float4 w4 = *(const float4*)&WA[k * 260 + ((h4 ^ kq) << 2)];
            e0[i] += tanha(w4.x + uA.x) * v4.x + tanha(w4.y + uA.y) * v4.y
                   + tanha(w4.z + uA.z) * v4.z + tanha(w4.w + uA.w) * v4.w;
            e1[i] += tanha(w4.x + uB.x) * v4.x + tanha(w4.y + uB.y) * v4.y
                   + tanha(w4.z + uB.z) * v4.z + tanha(w4.w + uB.w) * v4.w;
        }
    }
#pragma unroll
    for (int i = 0; i < 8; ++i) {
        ES[t0 * 68 + i * 8 + kq] = e0[i];
        ES[(t0 + 1) * 68 + i * 8 + kq] = e1[i];
    }
    __syncthreads();

    const float* encB = enc + (size_t)b * 64 * 256;
    for (int idx = tid; idx < 4096; idx += 256) {
        int k = idx >> 6, h4 = idx & 63;
        *(float4*)&WA[k * 260 + (h4 << 2)] = __ldg((const float4*)encB + idx);
    }
    __syncthreads();

    if (tid < 64) {
        float* er = &ES[tid * 68];
        float mx = -1e30f;
        for (int k = 0; k < 64; ++k) mx = fmaxf(mx, er[k]);
        float s = 0.f;
        for (int k = 0; k < 64; ++k) { float e = __expf(er[k] - mx); er[k] = e; s += e; }
        float inv = 1.f / s;
        for (int k = 0; k < 64; ++k) er[k] *= inv;
    }
    __syncthreads();

    const int tq2 = tid >> 4, hq = tid & 15;
    const int tb = tq2 * 4;
    float4 cacc[4][4];
#pragma unroll
    for (int dt = 0; dt < 4; ++dt)
#pragma unroll
        for (int jj = 0; jj < 4; ++jj) cacc[dt][jj] = make_float4(0.f, 0.f, 0.f, 0.f);

    for (int k = 0; k < 64; ++k) {
        float al[4];
#pragma unroll
        for (int dt = 0; dt < 4; ++dt) al[dt] = ES[(tb + dt) * 68 + k];
        float4 ev[4];
#pragma unroll
        for (int jj = 0; jj < 4; ++jj) ev[jj] = *(const float4*)&WA[k * 260 + hq * 16 + jj * 4];
#pragma unroll
        for (int dt = 0; dt < 4; ++dt)
#pragma unroll
            for (int jj = 0; jj < 4; ++jj) cacc[dt][jj] = ffma4(al[dt], ev[jj], cacc[dt][jj]);
    }
#pragma unroll
    for (int dt = 0; dt < 4; ++dt)
#pragma unroll
        for (int jj = 0; jj < 4; ++jj)
            *(float4*)&ctx[(size_t)(b * 64 + tb + dt) * 256 + hq * 16 + jj * 4] = cacc[dt][jj];
}

// ---------------- launch ----------------
extern "C" void kernel_launch(void* const* d_in, const int* in_sizes, int n_in,
                              void* d_out, int out_size)
{
    const int*   x     = (const int*)  d_in[0];
    const float* embed = (const float*)d_in[1];
    const float* w_ih0 = (const float*)d_in[2];
    const float* w_hh0 = (const float*)d_in[3];
    const float* b_ih0 = (const float*)d_in[4];
    const float* b_hh0 = (const float*)d_in[5];
    const float* w_ih1 = (const float*)d_in[6];
    const float* w_hh1 = (const float*)d_in[7];
    const float* b_ih1 = (const float*)d_in[8];
    const float* b_hh1 = (const float*)d_in[9];
    const float* W_a   = (const float*)d_in[10];
    const float* U_a   = (const float*)d_in[11];
    const float* v_a   = (const float*)d_in[12];
    const float* fc_W  = (const float*)d_in[13];
    const float* fc_b  = (const float*)d_in[14];

    float* out = (float*)d_out;                 // logits (B,T,V) then h_last (B,H)
    float* hlast = out + (size_t)BB * TT * VV;

    float *xp, *seq, *enc, *wa, *ua, *ctx;
    cudaGetSymbolAddress((void**)&xp,  g_xp);
    cudaGetSymbolAddress((void**)&seq, g_seq);
    cudaGetSymbolAddress((void**)&enc, g_enc);
    cudaGetSymbolAddress((void**)&wa,  g_Wa);
    cudaGetSymbolAddress((void**)&ua,  g_Ua);
    cudaGetSymbolAddress((void**)&ctx, g_ctx);

    cudaFuncSetAttribute(attn_k, cudaFuncAttributeMaxDynamicSharedMemorySize, AT_SMEM_BYTES);

    const int M = BB * TT;  // 8192

    // 1. xp0 = embed[x] @ w_ih0^T + b_ih0    (gather fused)
    gemm_k<<<dim3(M / 128, G3H / 64), 256>>>(embed, HH, x, w_ih0, HH, b_ih0, xp, G3H, HH, 0);
    // 2. scan layer 0 (32 clusters x 4 CTAs)
    scan_k<<<128, 256>>>(xp, w_hh0, b_hh0, seq, nullptr);
    // 3. xp1 = seq @ w_ih1^T + b_ih1
    gemm_k<<<dim3(M / 128, G3H / 64), 256>>>(seq, HH, nullptr, w_ih1, HH, b_ih1, xp, G3H, HH, 0);
    // 4. scan layer 1 -> enc, h_last
    scan_k<<<128, 256>>>(xp, w_hh1, b_hh1, enc, hlast);
    // 5/6. attention projections
    gemm_k<<<dim3(M / 128, HH / 64), 256>>>(enc, HH, nullptr, W_a, HH, nullptr, wa, HH, HH, 0);
    gemm_k<<<dim3(M / 128, HH / 64), 256>>>(enc, HH, nullptr, U_a, HH, nullptr, ua, HH, HH, 0);
    // 7. attention -> ctx
    attn_k<<<BB, 256, AT_SMEM_BYTES>>>(wa, ua, enc, v_a, ctx);
    // 8/9. logits = enc @ fcW[:, :H]^T + b ; += ctx @ fcW[:, H:]^T
    gemm_k<<<dim3(M / 128, VV / 64), 256>>>(enc, HH, nullptr, fc_W, 2 * HH, fc_b, out, VV, HH, 0);
    gemm_k<<<dim3(M / 128, VV / 64), 256>>>(ctx, HH, nullptr, fc_W + HH, 2 * HH, nullptr, out, VV, HH, 1);
}

// round 12
// speedup vs baseline: 1.0512x; 1.0512x over previous
#include <cuda_runtime.h>
#include <cuda_bf16.h>
#include <cstdint>
#include <cstddef>

#define BB 128
#define TT 64
#define HH 256
#define VV 128
#define G3H 768

// ---------------- persistent scratch ----------------
__device__ float g_xp [BB*TT*G3H];     // input projections (both layers, reused)
__device__ float g_seq[BB*TT*HH];      // layer-0 output
__device__ float g_enc[BB*TT*HH];      // layer-1 output (encoder)
__device__ float g_Wa [BB*TT*HH];
__device__ float g_Ua [BB*TT*HH];
__device__ float g_ctx[BB*TT*HH];

// ---------------- helpers ----------------
union F2U { float2 f; unsigned long long u; };

__device__ __forceinline__ float2 ffma2(float2 a, float2 b, float2 c) {
    F2U A, B, C, D; A.f = a; B.f = b; C.f = c;
    asm("fma.rn.f32x2 %0, %1, %2, %3;" : "=l"(D.u) : "l"(A.u), "l"(B.u), "l"(C.u));
    return D.f;
}

__device__ __forceinline__ float4 ffma4(float a, float4 b, float4 c) {
    float2 p = ffma2(make_float2(a, a), make_float2(b.x, b.y), make_float2(c.x, c.y));
    float2 q = ffma2(make_float2(a, a), make_float2(b.z, b.w), make_float2(c.z, c.w));
    return make_float4(p.x, p.y, q.x, q.y);
}

__device__ __forceinline__ float tanha(float x) {
    float y; asm("tanh.approx.f32 %0, %1;" : "=f"(y) : "f"(x)); return y;
}

__device__ __forceinline__ float sigm(float x) {
    return 1.f / (1.f + __expf(-x));
}

__device__ __forceinline__ uint32_t smem_u32(const void* p) {
    uint32_t a;
    asm("{ .reg .u64 t; cvta.to.shared.u64 t, %1; cvt.u32.u64 %0, t; }" : "=r"(a) : "l"(p));
    return a;
}

#define MBARRIER_INIT(addr, cnt) \
    asm volatile("mbarrier.init.shared.b64 [%0], %1;" :: "r"(addr), "r"(cnt) : "memory")

#define MBARRIER_EXPECT_TX(addr, tx) \
    asm volatile("mbarrier.arrive.expect_tx.shared.b64 _, [%0], %1;" :: "r"(addr), "r"(tx) : "memory")

#define MBARRIER_WAIT_PARITY(addr, par) do {                                        \
    uint32_t _m = (addr); uint32_t _p = (par); uint32_t _done;                      \
    asm volatile("{\n\t.reg .pred p;\n\t"                                           \
        "mbarrier.try_wait.parity.acquire.cta.shared::cta.b64 p, [%1], %2;\n\t"     \
        "selp.b32 %0, 1, 0, p;\n\t}"                                                \
        : "=r"(_done) : "r"(_m), "r"(_p) : "memory");                               \
    if (!_done) {                                                                   \
        asm volatile("{\n\t.reg .pred P1;\n\t"                                      \
            "WL_%=:\n\t"                                                            \
            "mbarrier.try_wait.parity.acquire.cta.shared::cta.b64 P1, [%0], %1, 0x989680;\n\t" \
            "@P1 bra.uni WD_%=;\n\t"                                                \
            "bra.uni WL_%=;\n\t"                                                    \
            "WD_%=:\n\t}" :: "r"(_m), "r"(_p) : "memory");                          \
    }                                                                               \
} while (0)

#define ST_ASYNC_B32(raddr, uval, rmbar) \
    asm volatile("st.async.shared::cluster.mbarrier::complete_tx::bytes.b32 [%0], %1, [%2];" \
        :: "r"(raddr), "r"(uval), "r"(rmbar) : "memory")

#define MAPA_U32(dst, laddr, rank) \
    asm("mapa.shared::cluster.u32 %0, %1, %2;" : "=r"(dst) : "r"(laddr), "r"(rank))

#define CLUSTER_SYNC() do {                                              \
    asm volatile("barrier.cluster.arrive.aligned;" ::: "memory");        \
    asm volatile("barrier.cluster.wait.aligned;" ::: "memory");          \
} while (0)

// ---------------- GEMM: C[m,n] = sum_k A[m,k]*W[n,k] (+bias | +=C) ----------------
// BM=128 BN=64 BK=16, 256 threads, 8x4 per thread, f32x2 FMA, register-staged
// k-tile pipelining. gather != null: A row m is A + gather[m]*lda.
__global__ void __launch_bounds__(256)
gemm_k(const float* __restrict__ A, int lda, const int* __restrict__ gather,
       const float* __restrict__ W, int ldw,
       const float* __restrict__ bias,
       float* __restrict__ C, int ldc, int K, int accumulate)
{
    __shared__ float As[16 * 132];
    __shared__ float Bs[16 * 68];

    const int tid = threadIdx.x;
    const int tx = tid & 15;           // n
    const int ty = tid >> 4;           // m
    const int mbase = blockIdx.x * 128;
    const int nbase = blockIdx.y * 64;

    const int ra = tid >> 2;           // A rows: ra and ra+64
    const int c4 = tid & 3;            // float4 column within 16-wide k-tile
    const int m0 = mbase + ra;
    const int m1 = mbase + ra + 64;
    const float* arow0 = A + (size_t)(gather ? gather[m0] : m0) * lda;
    const float* arow1 = A + (size_t)(gather ? gather[m1] : m1) * lda;
    const float* wrow  = W + (size_t)(nbase + ra) * ldw;

    float4 acc[8];
#pragma unroll
    for (int i = 0; i < 8; ++i) acc[i] = make_float4(0.f, 0.f, 0.f, 0.f);

    const int ktiles = K >> 4;
    float4 Av0 = __ldg((const float4*)(arow0 + c4 * 4));
    float4 Av1 = __ldg((const float4*)(arow1 + c4 * 4));
    float4 Bv  = __ldg((const float4*)(wrow  + c4 * 4));

    for (int kt = 0; kt < ktiles; ++kt) {
        As[(c4 * 4 + 0) * 132 + ra]      = Av0.x;
        As[(c4 * 4 + 1) * 132 + ra]      = Av0.y;
        As[(c4 * 4 + 2) * 132 + ra]      = Av0.z;
        As[(c4 * 4 + 3) * 132 + ra]      = Av0.w;
        As[(c4 * 4 + 0) * 132 + ra + 64] = Av1.x;
        As[(c4 * 4 + 1) * 132 + ra + 64] = Av1.y;
        As[(c4 * 4 + 2) * 132 + ra + 64] = Av1.z;
        As[(c4 * 4 + 3) * 132 + ra + 64] = Av1.w;
        Bs[(c4 * 4 + 0) * 68 + ra] = Bv.x;
        Bs[(c4 * 4 + 1) * 68 + ra] = Bv.y;
        Bs[(c4 * 4 + 2) * 68 + ra] = Bv.z;
        Bs[(c4 * 4 + 3) * 68 + ra] = Bv.w;
        __syncthreads();

        if (kt + 1 < ktiles) {
            Av0 = __ldg((const float4*)(arow0 + (kt + 1) * 16 + c4 * 4));
            Av1 = __ldg((const float4*)(arow1 + (kt + 1) * 16 + c4 * 4));
            Bv  = __ldg((const float4*)(wrow  + (kt + 1) * 16 + c4 * 4));
        }

#pragma unroll
        for (int k = 0; k < 16; ++k) {
            float4 a0 = *(const float4*)&As[k * 132 + ty * 8];
            float4 a1 = *(const float4*)&As[k * 132 + ty * 8 + 4];
            float4 b4 = *(const float4*)&Bs[k * 68 + tx * 4];
            acc[0] = ffma4(a0.x, b4, acc[0]);
            acc[1] = ffma4(a0.y, b4, acc[1]);
            acc[2] = ffma4(a0.z, b4, acc[2]);
            acc[3] = ffma4(a0.w, b4, acc[3]);
            acc[4] = ffma4(a1.x, b4, acc[4]);
            acc[5] = ffma4(a1.y, b4, acc[5]);
            acc[6] = ffma4(a1.z, b4, acc[6]);
            acc[7] = ffma4(a1.w, b4, acc[7]);
        }
        __syncthreads();
    }

    const int n0 = nbase + tx * 4;
    float4 bv = make_float4(0.f, 0.f, 0.f, 0.f);
    if (bias) bv = *(const float4*)&bias[n0];
#pragma unroll
    for (int mi = 0; mi < 8; ++mi) {
        int m = mbase + ty * 8 + mi;
        float4* cp = (float4*)&C[(size_t)m * ldc + n0];
        float4 o = acc[mi];
        if (accumulate) {
            float4 old = *cp;
            o.x += old.x; o.y += old.y; o.z += old.z; o.w += old.w;
        } else {
            o.x += bv.x; o.y += bv.y; o.z += bv.z; o.w += bv.w;
        }
        *cp = o;
    }
}

// ---------------- GRU scan: 32 clusters x 4 CTAs, smem weights, DSMEM h ----------------
// Thread (j, b) owns output row jg = rank*64+j for batch b0+b: full 256-k dot
// product, no cross-lane reduction. Weights live in smem transposed as
// ws[gate][k4][j] so a warp (8 j x 4 b) reads one contiguous 128B per LDS.128
// (4-way broadcast, conflict-free). h exchanged via st.async as before.
#define SCAN_WS_BYTES   (3 * 64 * 64 * 16)            // 196608
#define SCAN_HB_FLOATS  (2 * 4 * 260)                 // padded stride 260
#define SCAN_HB_BYTES   (SCAN_HB_FLOATS * 4)          // 8320
#define SCAN_SMEM_BYTES (SCAN_WS_BYTES + SCAN_HB_BYTES + 16)

__global__ void __launch_bounds__(256, 1) __cluster_dims__(4, 1, 1)
scan_k(const float* __restrict__ xp, const float* __restrict__ w_hh,
       const float* __restrict__ b_hh, float* __restrict__ seq,
       float* __restrict__ hlast)
{
    extern __shared__ __align__(16) unsigned char sm_raw[];
    float4* ws = (float4*)sm_raw;                               // [3][64][64]
    float*  hb = (float*)(sm_raw + SCAN_WS_BYTES);              // [2][4][260]
    unsigned long long* mbar =
        (unsigned long long*)(sm_raw + SCAN_WS_BYTES + SCAN_HB_BYTES);

    const int g   = blockIdx.x >> 2;
    const int tid = threadIdx.x;
    const int j   = tid >> 2;                 // 0..63  output row (local)
    const int b   = tid & 3;                  // local batch lane
    uint32_t rank;
    asm("mov.u32 %0, %%cluster_ctarank;" : "=r"(rank));
    const int jg = (int)rank * 64 + j;
    const int b0 = g * 4;

    // ---- prologue: load + transpose w_hh slice into smem ----
    // global row (gate*256 + rank*64 + jj), col k; smem ws[(gate*64+k4)*64+jj]
    for (int idx = tid; idx < 3 * 64 * 64; idx += 256) {
        int gg = idx >> 12;
        int jj = (idx >> 6) & 63;
        int kf = idx & 63;
        float4 v = __ldg((const float4*)(w_hh +
                     (size_t)(gg * 256 + (int)rank * 64 + jj) * 256) + kf);
        ws[(gg * 64 + kf) * 64 + jj] = v;
    }

    const float bh0 = b_hh[jg], bh1 = b_hh[256 + jg], bh2 = b_hh[512 + jg];

    const uint32_t mb0 = smem_u32(&mbar[0]);
    const uint32_t myh = smem_u32(&hb[(size_t)b * 260 + jg]);   // parity-0 slot
    uint32_t rh[4], rm[4];
#pragma unroll
    for (int r = 0; r < 4; ++r) { MAPA_U32(rh[r], myh, r); MAPA_U32(rm[r], mb0, r); }

    if (tid == 0) { MBARRIER_INIT(mb0, 1); MBARRIER_INIT(mb0 + 8, 1); }
    __syncthreads();
    CLUSTER_SYNC();                       // all mbars + ws live before any st.async
    if (tid == 0) {
        MBARRIER_EXPECT_TX(mb0, 4096);
        MBARRIER_EXPECT_TX(mb0 + 8, 4096);
    }

    const float* xpb = xp + (size_t)(b0 + b) * TT * G3H;
    float hprev = 0.f;
    int ph0 = 0, ph1 = 0;

    for (int t = 0; t < TT; ++t) {
        // prefetch xp for this (b, t) — hidden under wait + matvec
        const float* xr_p = xpb + (size_t)t * G3H;
        const float xr = __ldcg(xr_p + jg);
        const float xz = __ldcg(xr_p + 256 + jg);
        const float xn = __ldcg(xr_p + 512 + jg);

        float hr, hz, hn;
        if (t == 0) {
            hr = bh0; hz = bh1; hn = bh2;           // h == 0
        } else {
            const int ip = (t - 1) & 1;
            if (ip == 0) { MBARRIER_WAIT_PARITY(mb0, ph0);     ph0 ^= 1; }
            else         { MBARRIER_WAIT_PARITY(mb0 + 8, ph1); ph1 ^= 1; }
            if (tid == 0) MBARRIER_EXPECT_TX(mb0 + 8 * ip, 4096);  // re-arm

            const float4* h4 = (const float4*)(hb + (size_t)ip * 1040 + (size_t)b * 260);
            const float4* w0 = ws + j;              // [kf*64 + j], gate stride 4096
            float2 a00 = make_float2(0.f, 0.f), a01 = make_float2(0.f, 0.f);
            float2 a10 = make_float2(0.f, 0.f), a11 = make_float2(0.f, 0.f);
            float2 a20 = make_float2(0.f, 0.f), a21 = make_float2(0.f, 0.f);
#pragma unroll 8
            for (int kf = 0; kf < 64; ++kf) {
                float4 hv  = h4[kf];
                float4 wr_ = w0[kf * 64];
                float4 wz_ = w0[kf * 64 + 4096];
                float4 wn_ = w0[kf * 64 + 8192];
                float2 hxy = make_float2(hv.x, hv.y);
                float2 hzw = make_float2(hv.z, hv.w);
                a00 = ffma2(make_float2(wr_.x, wr_.y), hxy, a00);
                a01 = ffma2(make_float2(wr_.z, wr_.w), hzw, a01);
                a10 = ffma2(make_float2(wz_.x, wz_.y), hxy, a10);
                a11 = ffma2(make_float2(wz_.z, wz_.w), hzw, a11);
                a20 = ffma2(make_float2(wn_.x, wn_.y), hxy, a20);
                a21 = ffma2(make_float2(wn_.z, wn_.w), hzw, a21);
            }
            hr = a00.x + a00.y + a01.x + a01.y + bh0;
            hz = a10.x + a10.y + a11.x + a11.y + bh1;
            hn = a20.x + a20.y + a21.x + a21.y + bh2;
        }

        const float r = sigm(xr + hr);
        const float z = sigm(xz + hz);
        const float n = tanhf(xn + r * hn);
        const float hnew = (1.f - z) * n + z * hprev;
        hprev = hnew;

        __stcg(&seq[((size_t)(b0 + b) * TT + t) * HH + jg], hnew);
        if (hlast != nullptr && t == TT - 1)
            __stcg(&hlast[(size_t)(b0 + b) * HH + jg], hnew);

        // broadcast my h value to all 4 CTAs' buffer[t&1]
        const uint32_t po = (uint32_t)(t & 1) * 4160u;      // 1040 floats
        const uint32_t uval = __float_as_uint(hnew);
#pragma unroll
        for (int r2 = 0; r2 < 4; ++r2)
            ST_ASYNC_B32(rh[r2] + po, uval, rm[r2] + (uint32_t)(t & 1) * 8u);
    }

    // drain: consume the final phase so no st.async targets our smem after exit
    MBARRIER_WAIT_PARITY(mb0 + 8, ph1);
    CLUSTER_SYNC();
}

// ---------------- attention (CTA per batch) ----------------
#define AT_SMEM_FLOATS (2 * 64 * 260 + 64 * 68 + 256)
#define AT_SMEM_BYTES  (AT_SMEM_FLOATS * 4)

__global__ void __launch_bounds__(256, 1)
attn_k(const float* __restrict__ Wa, const float* __restrict__ Ua,
       const float* __restrict__ enc, const float* __restrict__ va,
       float* __restrict__ ctx)
{
    extern __shared__ float sm[];
    float* WA = sm;
    float* UA = sm + 64 * 260;
    float* ES = sm + 2 * 64 * 260;
    float* VS = ES + 64 * 68;

    const int b = blockIdx.x;
    const int tid = threadIdx.x;
    const float* waB = Wa + (size_t)b * 64 * 256;
    const float* uaB = Ua + (size_t)b * 64 * 256;

    for (int idx = tid; idx < 4096; idx += 256) {
        int k = idx >> 6, h4 = idx & 63;
        float4 w4 = __ldg((const float4*)waB + idx);
        *(float4*)&WA[k * 260 + ((h4 ^ (k & 7)) << 2)] = w4;   // xor swizzle
        float4 u4 = __ldg((const float4*)uaB + idx);
        *(float4*)&UA[k * 260 + (h4 << 2)] = u4;
    }
    if (tid < 64) *(float4*)&VS[tid * 4] = __ldg((const float4*)va + tid);
    __syncthreads();

    const int tq = tid >> 3, kq = tid & 7;
    const int t0 = tq * 2;
    float e0[8], e1[8];
#pragma unroll
    for (int i = 0; i < 8; ++i) { e0[i] = 0.f; e1[i] = 0.f; }

    for (int h4 = 0; h4 < 64; ++h4) {
        float4 v4 = *(const float4*)&VS[h4 * 4];
        float4 uA = *(const float4*)&UA[t0 * 260 + h4 * 4];
        float4 uB = *(const float4*)&UA[(t0 + 1) * 260 + h4 * 4];
#pragma unroll
        for (int i = 0; i < 8; ++i) {
            int k = i * 8 + kq;
            float4 w4 = *(const float4*)&WA[k * 260 + ((h4 ^ kq) << 2)];
            e0[i] += tanha(w4.x + uA.x) * v4.x + tanha(w4.y + uA.y) * v4.y
                   + tanha(w4.z + uA.z) * v4.z + tanha(w4.w + uA.w) * v4.w;
            e1[i] += tanha(w4.x + uB.x) * v4.x + tanha(w4.y + uB.y) * v4.y
                   + tanha(w4.z + uB.z) * v4.z + tanha(w4.w + uB.w) * v4.w;
        }
    }
#pragma unroll
    for (int i = 0; i < 8; ++i) {
        ES[t0 * 68 + i * 8 + kq] = e0[i];
        ES[(t0 + 1) * 68 + i * 8 + kq] = e1[i];
    }
    __syncthreads();

    const float* encB = enc + (size_t)b * 64 * 256;
    for (int idx = tid; idx < 4096; idx += 256) {
        int k = idx >> 6, h4 = idx & 63;
        *(float4*)&WA[k * 260 + (h4 << 2)] = __ldg((const float4*)encB + idx);
    }
    __syncthreads();

    if (tid < 64) {
        float* er = &ES[tid * 68];
        float mx = -1e30f;
        for (int k = 0; k < 64; ++k) mx = fmaxf(mx, er[k]);
        float s = 0.f;
        for (int k = 0; k < 64; ++k) { float e = __expf(er[k] - mx); er[k] = e; s += e; }
        float inv = 1.f / s;
        for (int k = 0; k < 64; ++k) er[k] *= inv;
    }
    __syncthreads();

    const int tq2 = tid >> 4, hq = tid & 15;
    const int tb = tq2 * 4;
    float4 cacc[4][4];
#pragma unroll
    for (int dt = 0; dt < 4; ++dt)
#pragma unroll
        for (int jj = 0; jj < 4; ++jj) cacc[dt][jj] = make_float4(0.f, 0.f, 0.f, 0.f);

    for (int k = 0; k < 64; ++k) {
        float al[4];
#pragma unroll
        for (int dt = 0; dt < 4; ++dt) al[dt] = ES[(tb + dt) * 68 + k];
        float4 ev[4];
#pragma unroll
        for (int jj = 0; jj < 4; ++jj) ev[jj] = *(const float4*)&WA[k * 260 + hq * 16 + jj * 4];
#pragma unroll
        for (int dt = 0; dt < 4; ++dt)
#pragma unroll
            for (int jj = 0; jj < 4; ++jj) cacc[dt][jj] = ffma4(al[dt], ev[jj], cacc[dt][jj]);
    }
#pragma unroll
    for (int dt = 0; dt < 4; ++dt)
#pragma unroll
        for (int jj = 0; jj < 4; ++jj)
            *(float4*)&ctx[(size_t)(b * 64 + tb + dt) * 256 + hq * 16 + jj * 4] = cacc[dt][jj];
}

// ---------------- launch ----------------
extern "C" void kernel_launch(void* const* d_in, const int* in_sizes, int n_in,
                              void* d_out, int out_size)
{
    const int*   x     = (const int*)  d_in[0];
    const float* embed = (const float*)d_in[1];
    const float* w_ih0 = (const float*)d_in[2];
    const float* w_hh0 = (const float*)d_in[3];
    const float* b_ih0 = (const float*)d_in[4];
    const float* b_hh0 = (const float*)d_in[5];
    const float* w_ih1 = (const float*)d_in[6];
    const float* w_hh1 = (const float*)d_in[7];
    const float* b_ih1 = (const float*)d_in[8];
    const float* b_hh1 = (const float*)d_in[9];
    const float* W_a   = (const float*)d_in[10];
    const float* U_a   = (const float*)d_in[11];
    const float* v_a   = (const float*)d_in[12];
    const float* fc_W  = (const float*)d_in[13];
    const float* fc_b  = (const float*)d_in[14];

    float* out = (float*)d_out;                 // logits (B,T,V) then h_last (B,H)
    float* hlast = out + (size_t)BB * TT * VV;

    float *xp, *seq, *enc, *wa, *ua, *ctx;
    cudaGetSymbolAddress((void**)&xp,  g_xp);
    cudaGetSymbolAddress((void**)&seq, g_seq);
    cudaGetSymbolAddress((void**)&enc, g_enc);
    cudaGetSymbolAddress((void**)&wa,  g_Wa);
    cudaGetSymbolAddress((void**)&ua,  g_Ua);
    cudaGetSymbolAddress((void**)&ctx, g_ctx);

    cudaFuncSetAttribute(attn_k, cudaFuncAttributeMaxDynamicSharedMemorySize, AT_SMEM_BYTES);
    cudaFuncSetAttribute(scan_k, cudaFuncAttributeMaxDynamicSharedMemorySize, SCAN_SMEM_BYTES);

    const int M = BB * TT;  // 8192

    // 1. xp0 = embed[x] @ w_ih0^T + b_ih0    (gather fused)
    gemm_k<<<dim3(M / 128, G3H / 64), 256>>>(embed, HH, x, w_ih0, HH, b_ih0, xp, G3H, HH, 0);
    // 2. scan layer 0 (32 clusters x 4 CTAs, smem weights)
    scan_k<<<128, 256, SCAN_SMEM_BYTES>>>(xp, w_hh0, b_hh0, seq, nullptr);
    // 3. xp1 = seq @ w_ih1^T + b_ih1
    gemm_k<<<dim3(M / 128, G3H / 64), 256>>>(seq, HH, nullptr, w_ih1, HH, b_ih1, xp, G3H, HH, 0);
    // 4. scan layer 1 -> enc, h_last
    scan_k<<<128, 256, SCAN_SMEM_BYTES>>>(xp, w_hh1, b_hh1, enc, hlast);
    // 5/6. attention projections
    gemm_k<<<dim3(M / 128, HH / 64), 256>>>(enc, HH, nullptr, W_a, HH, nullptr, wa, HH, HH, 0);
    gemm_k<<<dim3(M / 128, HH / 64), 256>>>(enc, HH, nullptr, U_a, HH, nullptr, ua, HH, HH, 0);
    // 7. attention -> ctx
    attn_k<<<BB, 256, AT_SMEM_BYTES>>>(wa, ua, enc, v_a, ctx);
    // 8/9. logits = enc @ fcW[:, :H]^T + b ; += ctx @ fcW[:, H:]^T
    gemm_k<<<dim3(M / 128, VV / 64), 256>>>(enc, HH, nullptr, fc_W, 2 * HH, fc_b, out, VV, HH, 0);
    gemm_k<<<dim3(M / 128, VV / 64), 256>>>(ctx, HH, nullptr, fc_W + HH, 2 * HH, nullptr, out, VV, HH, 1);
}

// round 13
// speedup vs baseline: 1.1244x; 1.0696x over previous
#include <cuda_runtime.h>
#include <cuda_bf16.h>
#include <cstdint>
#include <cstddef>

#define BB 128
#define TT 64
#define HH 256
#define VV 128
#define G3H 768

// ---------------- persistent scratch ----------------
__device__ float g_xp [BB*TT*G3H];     // input projections (both layers, reused)
__device__ float g_seq[BB*TT*HH];      // layer-0 output
__device__ float g_enc[BB*TT*HH];      // layer-1 output (encoder)
__device__ float g_Wa [BB*TT*HH];
__device__ float g_Ua [BB*TT*HH];
__device__ float g_ctx[BB*TT*HH];

// ---------------- helpers ----------------
union F2U { float2 f; unsigned long long u; };

__device__ __forceinline__ float2 ffma2(float2 a, float2 b, float2 c) {
    F2U A, B, C, D; A.f = a; B.f = b; C.f = c;
    asm("fma.rn.f32x2 %0, %1, %2, %3;" : "=l"(D.u) : "l"(A.u), "l"(B.u), "l"(C.u));
    return D.f;
}

__device__ __forceinline__ float4 ffma4(float a, float4 b, float4 c) {
    float2 p = ffma2(make_float2(a, a), make_float2(b.x, b.y), make_float2(c.x, c.y));
    float2 q = ffma2(make_float2(a, a), make_float2(b.z, b.w), make_float2(c.z, c.w));
    return make_float4(p.x, p.y, q.x, q.y);
}

__device__ __forceinline__ float tanha(float x) {
    float y; asm("tanh.approx.f32 %0, %1;" : "=f"(y) : "f"(x)); return y;
}

__device__ __forceinline__ float sigm(float x) {
    return 1.f / (1.f + __expf(-x));
}

__device__ __forceinline__ float4 shfl4(float4 v, int src) {
    float4 r;
    r.x = __shfl_sync(0xffffffffu, v.x, src);
    r.y = __shfl_sync(0xffffffffu, v.y, src);
    r.z = __shfl_sync(0xffffffffu, v.z, src);
    r.w = __shfl_sync(0xffffffffu, v.w, src);
    return r;
}

__device__ __forceinline__ uint32_t smem_u32(const void* p) {
    uint32_t a;
    asm("{ .reg .u64 t; cvta.to.shared.u64 t, %1; cvt.u32.u64 %0, t; }" : "=r"(a) : "l"(p));
    return a;
}

#define MBARRIER_INIT(addr, cnt) \
    asm volatile("mbarrier.init.shared.b64 [%0], %1;" :: "r"(addr), "r"(cnt) : "memory")

#define MBARRIER_EXPECT_TX(addr, tx) \
    asm volatile("mbarrier.arrive.expect_tx.shared.b64 _, [%0], %1;" :: "r"(addr), "r"(tx) : "memory")

#define MBARRIER_WAIT_PARITY(addr, par) do {                                        \
    uint32_t _m = (addr); uint32_t _p = (par); uint32_t _done;                      \
    asm volatile("{\n\t.reg .pred p;\n\t"                                           \
        "mbarrier.try_wait.parity.acquire.cta.shared::cta.b64 p, [%1], %2;\n\t"     \
        "selp.b32 %0, 1, 0, p;\n\t}"                                                \
        : "=r"(_done) : "r"(_m), "r"(_p) : "memory");                               \
    if (!_done) {                                                                   \
        asm volatile("{\n\t.reg .pred P1;\n\t"                                      \
            "WL_%=:\n\t"                                                            \
            "mbarrier.try_wait.parity.acquire.cta.shared::cta.b64 P1, [%0], %1, 0x989680;\n\t" \
            "@P1 bra.uni WD_%=;\n\t"                                                \
            "bra.uni WL_%=;\n\t"                                                    \
            "WD_%=:\n\t}" :: "r"(_m), "r"(_p) : "memory");                          \
    }                                                                               \
} while (0)

#define ST_ASYNC_B32(raddr, uval, rmbar) \
    asm volatile("st.async.shared::cluster.mbarrier::complete_tx::bytes.b32 [%0], %1, [%2];" \
        :: "r"(raddr), "r"(uval), "r"(rmbar) : "memory")

#define MAPA_U32(dst, laddr, rank) \
    asm("mapa.shared::cluster.u32 %0, %1, %2;" : "=r"(dst) : "r"(laddr), "r"(rank))

#define CLUSTER_SYNC() do {                                              \
    asm volatile("barrier.cluster.arrive.aligned;" ::: "memory");        \
    asm volatile("barrier.cluster.wait.aligned;" ::: "memory");          \
} while (0)

// ---------------- GEMM: C[m,n] = sum_k A[m,k]*W[n,k] (+bias | +=C) ----------------
// BM=128 BN=128 BK=16, 256 threads, 8x8 per thread, f32x2 FMA, register-staged
// k-tile pipelining. gather != null: A row m is A + gather[m]*lda.
__global__ void __launch_bounds__(256)
gemm_k(const float* __restrict__ A, int lda, const int* __restrict__ gather,
       const float* __restrict__ W, int ldw,
       const float* __restrict__ bias,
       float* __restrict__ C, int ldc, int K, int accumulate)
{
    __shared__ float As[16 * 132];
    __shared__ float Bs[16 * 132];

    const int tid = threadIdx.x;
    const int tx = tid & 15;           // n-octet
    const int ty = tid >> 4;           // m-octet
    const int mbase = blockIdx.x * 128;
    const int nbase = blockIdx.y * 128;

    const int ra = tid >> 2;           // rows ra and ra+64 (A and W)
    const int c4 = tid & 3;            // float4 column within 16-wide k-tile
    const int m0 = mbase + ra;
    const int m1 = mbase + ra + 64;
    const float* arow0 = A + (size_t)(gather ? gather[m0] : m0) * lda;
    const float* arow1 = A + (size_t)(gather ? gather[m1] : m1) * lda;
    const float* wrow0 = W + (size_t)(nbase + ra) * ldw;
    const float* wrow1 = W + (size_t)(nbase + ra + 64) * ldw;

    float4 acc[8][2];
#pragma unroll
    for (int i = 0; i < 8; ++i) {
        acc[i][0] = make_float4(0.f, 0.f, 0.f, 0.f);
        acc[i][1] = make_float4(0.f, 0.f, 0.f, 0.f);
    }

    const int ktiles = K >> 4;
    float4 Av0 = __ldg((const float4*)(arow0 + c4 * 4));
    float4 Av1 = __ldg((const float4*)(arow1 + c4 * 4));
    float4 Bv0 = __ldg((const float4*)(wrow0 + c4 * 4));
    float4 Bv1 = __ldg((const float4*)(wrow1 + c4 * 4));

    for (int kt = 0; kt < ktiles; ++kt) {
        As[(c4 * 4 + 0) * 132 + ra]      = Av0.x;
        As[(c4 * 4 + 1) * 132 + ra]      = Av0.y;
        As[(c4 * 4 + 2) * 132 + ra]      = Av0.z;
        As[(c4 * 4 + 3) * 132 + ra]      = Av0.w;
        As[(c4 * 4 + 0) * 132 + ra + 64] = Av1.x;
        As[(c4 * 4 + 1) * 132 + ra + 64] = Av1.y;
        As[(c4 * 4 + 2) * 132 + ra + 64] = Av1.z;
        As[(c4 * 4 + 3) * 132 + ra + 64] = Av1.w;
        Bs[(c4 * 4 + 0) * 132 + ra]      = Bv0.x;
        Bs[(c4 * 4 + 1) * 132 + ra]      = Bv0.y;
        Bs[(c4 * 4 + 2) * 132 + ra]      = Bv0.z;
        Bs[(c4 * 4 + 3) * 132 + ra]      = Bv0.w;
        Bs[(c4 * 4 + 0) * 132 + ra + 64] = Bv1.x;
        Bs[(c4 * 4 + 1) * 132 + ra + 64] = Bv1.y;
        Bs[(c4 * 4 + 2) * 132 + ra + 64] = Bv1.z;
        Bs[(c4 * 4 + 3) * 132 + ra + 64] = Bv1.w;
        __syncthreads();

        if (kt + 1 < ktiles) {
            Av0 = __ldg((const float4*)(arow0 + (kt + 1) * 16 + c4 * 4));
            Av1 = __ldg((const float4*)(arow1 + (kt + 1) * 16 + c4 * 4));
            Bv0 = __ldg((const float4*)(wrow0 + (kt + 1) * 16 + c4 * 4));
            Bv1 = __ldg((const float4*)(wrow1 + (kt + 1) * 16 + c4 * 4));
        }

#pragma unroll
        for (int k = 0; k < 16; ++k) {
            float4 a0 = *(const float4*)&As[k * 132 + ty * 8];
            float4 a1 = *(const float4*)&As[k * 132 + ty * 8 + 4];
            float4 b0 = *(const float4*)&Bs[k * 132 + tx * 8];
            float4 b1 = *(const float4*)&Bs[k * 132 + tx * 8 + 4];
            acc[0][0] = ffma4(a0.x, b0, acc[0][0]); acc[0][1] = ffma4(a0.x, b1, acc[0][1]);
            acc[1][0] = ffma4(a0.y, b0, acc[1][0]); acc[1][1] = ffma4(a0.y, b1, acc[1][1]);
            acc[2][0] = ffma4(a0.z, b0, acc[2][0]); acc[2][1] = ffma4(a0.z, b1, acc[2][1]);
            acc[3][0] = ffma4(a0.w, b0, acc[3][0]); acc[3][1] = ffma4(a0.w, b1, acc[3][1]);
            acc[4][0] = ffma4(a1.x, b0, acc[4][0]); acc[4][1] = ffma4(a1.x, b1, acc[4][1]);
            acc[5][0] = ffma4(a1.y, b0, acc[5][0]); acc[5][1] = ffma4(a1.y, b1, acc[5][1]);
            acc[6][0] = ffma4(a1.z, b0, acc[6][0]); acc[6][1] = ffma4(a1.z, b1, acc[6][1]);
            acc[7][0] = ffma4(a1.w, b0, acc[7][0]); acc[7][1] = ffma4(a1.w, b1, acc[7][1]);
        }
        __syncthreads();
    }

    const int n0 = nbase + tx * 8;
    float4 bv0 = make_float4(0.f, 0.f, 0.f, 0.f);
    float4 bv1 = bv0;
    if (bias) { bv0 = *(const float4*)&bias[n0]; bv1 = *(const float4*)&bias[n0 + 4]; }
#pragma unroll
    for (int mi = 0; mi < 8; ++mi) {
        int m = mbase + ty * 8 + mi;
        float4* cp = (float4*)&C[(size_t)m * ldc + n0];
        float4 o0 = acc[mi][0], o1 = acc[mi][1];
        if (accumulate) {
            float4 q0 = cp[0], q1 = cp[1];
            o0.x += q0.x; o0.y += q0.y; o0.z += q0.z; o0.w += q0.w;
            o1.x += q1.x; o1.y += q1.y; o1.z += q1.z; o1.w += q1.w;
        } else {
            o0.x += bv0.x; o0.y += bv0.y; o0.z += bv0.z; o0.w += bv0.w;
            o1.x += bv1.x; o1.y += bv1.y; o1.z += bv1.z; o1.w += bv1.w;
        }
        cp[0] = o0; cp[1] = o1;
    }
}

// ---------------- GRU scan: 32 clusters x 4 CTAs ----------------
// Thread (jg8 = tid>>3, kq = tid&7): j-pair {2*jg8, 2*jg8+1} x 4 batches x
// k-float4s {kq + 8i}. Weights read from smem EXACTLY ONCE per CTA per step
// (unique 128B phases). h preloaded to registers once per warp (lane l holds
// h[b=l&3][f4=(l>>2)+8r]) and distributed via shfl.idx (src = kq*4+b, reg i).
// 8-way xor-shuffle reduction over kq; lane kq finalizes (j2=kq>>2, b=kq&3).
#define SCAN_WS_BYTES   (3 * 64 * 64 * 16)            // 196608
#define SCAN_HB_FLOATS  (2 * 4 * 264)                 // padded stride 264
#define SCAN_HB_BYTES   (SCAN_HB_FLOATS * 4)          // 8448
#define SCAN_SMEM_BYTES (SCAN_WS_BYTES + SCAN_HB_BYTES + 16)

__global__ void __launch_bounds__(256, 1) __cluster_dims__(4, 1, 1)
scan_k(const float* __restrict__ xp, const float* __restrict__ w_hh,
       const float* __restrict__ b_hh, float* __restrict__ seq,
       float* __restrict__ hlast)
{
    extern __shared__ __align__(16) unsigned char sm_raw[];
    float4* ws = (float4*)sm_raw;                               // [3][64 j][64 f4]
    float*  hb = (float*)(sm_raw + SCAN_WS_BYTES);              // [2][4][264]
    unsigned long long* mbar =
        (unsigned long long*)(sm_raw + SCAN_WS_BYTES + SCAN_HB_BYTES);

    const int g   = blockIdx.x >> 2;
    const int tid = threadIdx.x;
    const int jg8 = tid >> 3;                 // 0..31  j-pair group
    const int kq  = tid & 7;                  // 0..7   k-slice
    const int jl0 = jg8 * 2;
    uint32_t rank;
    asm("mov.u32 %0, %%cluster_ctarank;" : "=r"(rank));
    const int b0 = g * 4;

    // warp-local h ownership: lane l holds h[b=l&3][f4=(l>>2)+8r]
    const int lane   = tid & 31;
    const int b_own  = lane & 3;
    const int blk    = lane >> 2;             // 0..7

    // output assignment: lane kq finalizes (j2 = kq>>2, b = kq&3)
    const int j2o   = kq >> 2;
    const int b_out = kq & 3;
    const int jlo   = jl0 + j2o;              // local j of output
    const int jgo   = (int)rank * 64 + jlo;   // global hidden index

    // ---- prologue: copy w_hh slice (row-major, identity in f4) ----
    for (int idx = tid; idx < 3 * 64 * 64; idx += 256) {
        int gg = idx >> 12;
        int jl = (idx >> 6) & 63;
        int f4 = idx & 63;
        ws[idx] = __ldg((const float4*)(w_hh +
                    (size_t)(gg * 256 + (int)rank * 64 + jl) * 256) + f4);
    }

    const float bh0 = b_hh[jgo], bh1 = b_hh[256 + jgo], bh2 = b_hh[512 + jgo];

    const uint32_t mb0 = smem_u32(&mbar[0]);
    const uint32_t myh = smem_u32(&hb[(size_t)b_out * 264 + jgo]);  // parity-0 slot
    uint32_t rh[4], rm[4];
#pragma unroll
    for (int r = 0; r < 4; ++r) { MAPA_U32(rh[r], myh, r); MAPA_U32(rm[r], mb0, r); }

    if (tid == 0) { MBARRIER_INIT(mb0, 1); MBARRIER_INIT(mb0 + 8, 1); }
    __syncthreads();
    CLUSTER_SYNC();                       // all mbars + ws live before any st.async
    if (tid == 0) {
        MBARRIER_EXPECT_TX(mb0, 4096);
        MBARRIER_EXPECT_TX(mb0 + 8, 4096);
    }

    const float* xpb = xp + (size_t)(b0 + b_out) * TT * G3H;
    const float4* wp = ws + (size_t)jl0 * 64 + kq;   // + g*4096 + j2*64 + 8i
    float hprev = 0.f;
    int ph0 = 0, ph1 = 0;

    for (int t = 0; t < TT; ++t) {
        // prefetch xp for this (b_out, t) — hidden under wait + matvec
        const float* xr_p = xpb + (size_t)t * G3H;
        const float xr = __ldcg(xr_p + jgo);
        const float xz = __ldcg(xr_p + 256 + jgo);
        const float xn = __ldcg(xr_p + 512 + jgo);

        float hr, hz, hn;
        if (t == 0) {
            hr = bh0; hz = bh1; hn = bh2;           // h == 0
        } else {
            const int ip = (t - 1) & 1;
            if (ip == 0) { MBARRIER_WAIT_PARITY(mb0, ph0);     ph0 ^= 1; }
            else         { MBARRIER_WAIT_PARITY(mb0 + 8, ph1); ph1 ^= 1; }
            if (tid == 0) MBARRIER_EXPECT_TX(mb0 + 8 * ip, 4096);  // re-arm

            // preload h to registers (one read of h per warp total)
            const float4* hrow = (const float4*)(hb + (size_t)ip * 1056 +
                                                 (size_t)b_own * 264);
            float4 hreg[8];
#pragma unroll
            for (int r = 0; r < 8; ++r) hreg[r] = hrow[blk + 8 * r];

            float2 acc[2][4][3];
#pragma unroll
            for (int j2 = 0; j2 < 2; ++j2)
#pragma unroll
                for (int b = 0; b < 4; ++b)
#pragma unroll
                    for (int gg = 0; gg < 3; ++gg)
                        acc[j2][b][gg] = make_float2(0.f, 0.f);

#pragma unroll
            for (int i = 0; i < 8; ++i) {
                float4 wv[2][3];
#pragma unroll
                for (int j2 = 0; j2 < 2; ++j2) {
#pragma unroll
                    for (int gg = 0; gg < 3; ++gg)
                        wv[j2][gg] = wp[gg * 4096 + j2 * 64 + 8 * i];
                }
#pragma unroll
                for (int b = 0; b < 4; ++b) {
                    float4 hv = shfl4(hreg[i], (kq << 2) | b);
                    float2 hxy = make_float2(hv.x, hv.y);
                    float2 hzw = make_float2(hv.z, hv.w);
#pragma unroll
                    for (int j2 = 0; j2 < 2; ++j2) {
#pragma unroll
                        for (int gg = 0; gg < 3; ++gg) {
                            acc[j2][b][gg] = ffma2(make_float2(wv[j2][gg].x, wv[j2][gg].y),
                                                   hxy, acc[j2][b][gg]);
                            acc[j2][b][gg] = ffma2(make_float2(wv[j2][gg].z, wv[j2][gg].w),
                                                   hzw, acc[j2][b][gg]);
                        }
                    }
                }
            }

            // horizontal + 8-way xor reduction over kq lanes
            float s[2][4][3];
#pragma unroll
            for (int j2 = 0; j2 < 2; ++j2)
#pragma unroll
                for (int b = 0; b < 4; ++b)
#pragma unroll
                    for (int gg = 0; gg < 3; ++gg) {
                        float v = acc[j2][b][gg].x + acc[j2][b][gg].y;
                        v += __shfl_xor_sync(0xffffffffu, v, 1);
                        v += __shfl_xor_sync(0xffffffffu, v, 2);
                        v += __shfl_xor_sync(0xffffffffu, v, 4);
                        s[j2][b][gg] = v;
                    }

            hr = bh0; hz = bh1; hn = bh2;
#pragma unroll
            for (int j2 = 0; j2 < 2; ++j2)
#pragma unroll
                for (int b = 0; b < 4; ++b)
                    if (kq == ((j2 << 2) | b)) {
                        hr += s[j2][b][0];
                        hz += s[j2][b][1];
                        hn += s[j2][b][2];
                    }
        }

        const float r = sigm(xr + hr);
        const float z = sigm(xz + hz);
        const float n = tanhf(xn + r * hn);
        const float hnew = (1.f - z) * n + z * hprev;
        hprev = hnew;

        __stcg(&seq[((size_t)(b0 + b_out) * TT + t) * HH + jgo], hnew);
        if (hlast != nullptr && t == TT - 1)
            __stcg(&hlast[(size_t)(b0 + b_out) * HH + jgo], hnew);

        // broadcast my h value to all 4 CTAs' buffer[t&1]
        const uint32_t po = (uint32_t)(t & 1) * 4224u;      // 1056 floats
        const uint32_t uval = __float_as_uint(hnew);
#pragma unroll
        for (int r2 = 0; r2 < 4; ++r2)
            ST_ASYNC_B32(rh[r2] + po, uval, rm[r2] + (uint32_t)(t & 1) * 8u);
    }

    // drain: consume the final phase so no st.async targets our smem after exit
    MBARRIER_WAIT_PARITY(mb0 + 8, ph1);
    CLUSTER_SYNC();
}

// ---------------- attention (CTA per batch) ----------------
#define AT_SMEM_FLOATS (2 * 64 * 260 + 64 * 68 + 256)
#define AT_SMEM_BYTES  (AT_SMEM_FLOATS * 4)

__global__ void __launch_bounds__(256, 1)
attn_k(const float* __restrict__ Wa, const float* __restrict__ Ua,
       const float* __restrict__ enc, const float* __restrict__ va,
       float* __restrict__ ctx)
{
    extern __shared__ float sm[];
    float* WA = sm;
    float* UA = sm + 64 * 260;
    float* ES = sm + 2 * 64 * 260;
    float* VS = ES + 64 * 68;

    const int b = blockIdx.x;
    const int tid = threadIdx.x;
    const float* waB = Wa + (size_t)b * 64 * 256;
    const float* uaB = Ua + (size_t)b * 64 * 256;

    for (int idx = tid; idx < 4096; idx += 256) {
        int k = idx >> 6, h4 = idx & 63;
        float4 w4 = __ldg((const float4*)waB + idx);
        *(float4*)&WA[k * 260 + ((h4 ^ (k & 7)) << 2)] = w4;   // xor swizzle
        float4 u4 = __ldg((const float4*)uaB + idx);
        *(float4*)&UA[k * 260 + (h4 << 2)] = u4;
    }
    if (tid < 64) *(float4*)&VS[tid * 4] = __ldg((const float4*)va + tid);
    __syncthreads();

    const int tq = tid >> 3, kq = tid & 7;
    const int t0 = tq * 2;
    float e0[8], e1[8];
#pragma unroll
    for (int i = 0; i < 8; ++i) { e0[i] = 0.f; e1[i] = 0.f; }

    for (int h4 = 0; h4 < 64; ++h4) {
        float4 v4 = *(const float4*)&VS[h4 * 4];
        float4 uA = *(const float4*)&UA[t0 * 260 + h4 * 4];
        float4 uB = *(const float4*)&UA[(t0 + 1) * 260 + h4 * 4];
#pragma unroll
        for (int i = 0; i < 8; ++i) {
            int k = i * 8 + kq;
            float4 w4 = *(const float4*)&WA[k * 260 + ((h4 ^ kq) << 2)];
            e0[i] += tanha(w4.x + uA.x) * v4.x + tanha(w4.y + uA.y) * v4.y
                   + tanha(w4.z + uA.z) * v4.z + tanha(w4.w + uA.w) * v4.w;
            e1[i] += tanha(w4.x + uB.x) * v4.x + tanha(w4.y + uB.y) * v4.y
                   + tanha(w4.z + uB.z) * v4.z + tanha(w4.w + uB.w) * v4.w;
        }
    }
#pragma unroll
    for (int i = 0; i < 8; ++i) {
        ES[t0 * 68 + i * 8 + kq] = e0[i];
        ES[(t0 + 1) * 68 + i * 8 + kq] = e1[i];
    }
    __syncthreads();

    const float* encB = enc + (size_t)b * 64 * 256;
    for (int idx = tid; idx < 4096; idx += 256) {
        int k = idx >> 6, h4 = idx & 63;
        *(float4*)&WA[k * 260 + (h4 << 2)] = __ldg((const float4*)encB + idx);
    }
    __syncthreads();

    if (tid < 64) {
        float* er = &ES[tid * 68];
        float mx = -1e30f;
        for (int k = 0; k < 64; ++k) mx = fmaxf(mx, er[k]);
        float s = 0.f;
        for (int k = 0; k < 64; ++k) { float e = __expf(er[k] - mx); er[k] = e; s += e; }
        float inv = 1.f / s;
        for (int k = 0; k < 64; ++k) er[k] *= inv;
    }
    __syncthreads();

    const int tq2 = tid >> 4, hq = tid & 15;
    const int tb = tq2 * 4;
    float4 cacc[4][4];
#pragma unroll
    for (int dt = 0; dt < 4; ++dt)
#pragma unroll
        for (int jj = 0; jj < 4; ++jj) cacc[dt][jj] = make_float4(0.f, 0.f, 0.f, 0.f);

    for (int k = 0; k < 64; ++k) {
        float al[4];
#pragma unroll
        for (int dt = 0; dt < 4; ++dt) al[dt] = ES[(tb + dt) * 68 + k];
        float4 ev[4];
#pragma unroll
        for (int jj = 0; jj < 4; ++jj) ev[jj] = *(const float4*)&WA[k * 260 + hq * 16 + jj * 4];
#pragma unroll
        for (int dt = 0; dt < 4; ++dt)
#pragma unroll
            for (int jj = 0; jj < 4; ++jj) cacc[dt][jj] = ffma4(al[dt], ev[jj], cacc[dt][jj]);
    }
#pragma unroll
    for (int dt = 0; dt < 4; ++dt)
#pragma unroll
        for (int jj = 0; jj < 4; ++jj)
            *(float4*)&ctx[(size_t)(b * 64 + tb + dt) * 256 + hq * 16 + jj * 4] = cacc[dt][jj];
}

// ---------------- launch ----------------
extern "C" void kernel_launch(void* const* d_in, const int* in_sizes, int n_in,
                              void* d_out, int out_size)
{
    const int*   x     = (const int*)  d_in[0];
    const float* embed = (const float*)d_in[1];
    const float* w_ih0 = (const float*)d_in[2];
    const float* w_hh0 = (const float*)d_in[3];
    const float* b_ih0 = (const float*)d_in[4];
    const float* b_hh0 = (const float*)d_in[5];
    const float* w_ih1 = (const float*)d_in[6];
    const float* w_hh1 = (const float*)d_in[7];
    const float* b_ih1 = (const float*)d_in[8];
    const float* b_hh1 = (const float*)d_in[9];
    const float* W_a   = (const float*)d_in[10];
    const float* U_a   = (const float*)d_in[11];
    const float* v_a   = (const float*)d_in[12];
    const float* fc_W  = (const float*)d_in[13];
    const float* fc_b  = (const float*)d_in[14];

    float* out = (float*)d_out;                 // logits (B,T,V) then h_last (B,H)
    float* hlast = out + (size_t)BB * TT * VV;

    float *xp, *seq, *enc, *wa, *ua, *ctx;
    cudaGetSymbolAddress((void**)&xp,  g_xp);
    cudaGetSymbolAddress((void**)&seq, g_seq);
    cudaGetSymbolAddress((void**)&enc, g_enc);
    cudaGetSymbolAddress((void**)&wa,  g_Wa);
    cudaGetSymbolAddress((void**)&ua,  g_Ua);
    cudaGetSymbolAddress((void**)&ctx, g_ctx);

    cudaFuncSetAttribute(attn_k, cudaFuncAttributeMaxDynamicSharedMemorySize, AT_SMEM_BYTES);
    cudaFuncSetAttribute(scan_k, cudaFuncAttributeMaxDynamicSharedMemorySize, SCAN_SMEM_BYTES);

    const int M = BB * TT;  // 8192

    // 1. xp0 = embed[x] @ w_ih0^T + b_ih0    (gather fused)
    gemm_k<<<dim3(M / 128, G3H / 128), 256>>>(embed, HH, x, w_ih0, HH, b_ih0, xp, G3H, HH, 0);
    // 2. scan layer 0 (32 clusters x 4 CTAs, smem weights read-once)
    scan_k<<<128, 256, SCAN_SMEM_BYTES>>>(xp, w_hh0, b_hh0, seq, nullptr);
    // 3. xp1 = seq @ w_ih1^T + b_ih1
    gemm_k<<<dim3(M / 128, G3H / 128), 256>>>(seq, HH, nullptr, w_ih1, HH, b_ih1, xp, G3H, HH, 0);
    // 4. scan layer 1 -> enc, h_last
    scan_k<<<128, 256, SCAN_SMEM_BYTES>>>(xp, w_hh1, b_hh1, enc, hlast);
    // 5/6. attention projections
    gemm_k<<<dim3(M / 128, HH / 128), 256>>>(enc, HH, nullptr, W_a, HH, nullptr, wa, HH, HH, 0);
    gemm_k<<<dim3(M / 128, HH / 128), 256>>>(enc, HH, nullptr, U_a, HH, nullptr, ua, HH, HH, 0);
    // 7. attention -> ctx
    attn_k<<<BB, 256, AT_SMEM_BYTES>>>(wa, ua, enc, v_a, ctx);
    // 8/9. logits = enc @ fcW[:, :H]^T + b ; += ctx @ fcW[:, H:]^T
    gemm_k<<<dim3(M / 128, VV / 128), 256>>>(enc, HH, nullptr, fc_W, 2 * HH, fc_b, out, VV, HH, 0);
    gemm_k<<<dim3(M / 128, VV / 128), 256>>>(ctx, HH, nullptr, fc_W + HH, 2 * HH, nullptr, out, VV, HH, 1);
}